// round 15
// baseline (speedup 1.0000x reference)
#include <cuda_runtime.h>
#include <cuda_fp16.h>
#include <cstdint>

#define N_NODES 100000
#define N_EDGES 1600000
#define N_GRAPHS 512

// ---------------- scratch (device globals; no allocation allowed) ----------
// g_degi is zero on first run (static init) and re-zeroed by pool_kernel at
// the end of every replay -> deterministic across graph replays.
__device__ int                g_degi[N_NODES];
__device__ unsigned long long g_edge[N_EDGES];     // packed src | dst<<32
__device__ uint2              g_h1h[N_NODES * 8];  // h1 = x@W1 (UNSCALED), fp16
__device__ uint2              g_agg1h[N_NODES * 8];// fp16 accumulators
__device__ uint2              g_h2h[N_NODES * 8];  // h2' = (in@W2)*dis, fp16
__device__ uint2              g_agg2h[N_NODES * 8];
__device__ float              g_gsum[N_GRAPHS];
__device__ float              g_gcnt[N_GRAPHS];
__device__ int                g_done;

// ---------------- f32x2 helpers (Blackwell packed FFMA) ---------------------
__device__ __forceinline__ unsigned long long pack2(float x) {
    unsigned long long r;
    asm("mov.b64 %0, {%1, %1};" : "=l"(r) : "r"(__float_as_uint(x)));
    return r;
}
__device__ __forceinline__ void ffma2(unsigned long long& d,
                                      unsigned long long a,
                                      unsigned long long b) {
    asm("fma.rn.f32x2 %0, %1, %2, %0;" : "+l"(d) : "l"(a), "l"(b));
}
__device__ __forceinline__ float2 unpack2(unsigned long long v) {
    float2 f;
    asm("mov.b64 {%0, %1}, %2;" : "=f"(f.x), "=f"(f.y) : "l"(v));
    return f;
}
__device__ __forceinline__ unsigned h2u(__half2 h) { return *(unsigned*)&h; }
__device__ __forceinline__ __half2 u2h2(unsigned u) { return *(__half2*)&u; }
__device__ __forceinline__ float2 u2f2(unsigned u) {
    return __half22float2(*(__half2*)&u);
}

// per-block dtype detection: warp ballot over first 64 u64 words of edge_index
__device__ __forceinline__ int detect_is64(const void* ei) {
    __shared__ int s_is64;
    if (threadIdx.x < 32) {
        const unsigned long long* p = (const unsigned long long*)ei;
        unsigned long long v0 = p[threadIdx.x];
        unsigned long long v1 = p[32 + threadIdx.x];
        unsigned m = __ballot_sync(0xffffffffu,
            (v0 >= (unsigned long long)N_NODES) || (v1 >= (unsigned long long)N_NODES));
        if (threadIdx.x == 0) s_is64 = m ? 0 : 1;
    }
    __syncthreads();
    return s_is64;
}

// ---------------- prep: detect + pack edges + degree hist + zero smalls -----
__global__ void prep_kernel(const void* ei) {
    int is64 = detect_is64(ei);
    if (blockIdx.x == 0) {
        for (int i = threadIdx.x; i < N_GRAPHS; i += 256) {
            g_gsum[i] = 0.f; g_gcnt[i] = 0.f;
        }
        if (threadIdx.x == 0) g_done = 0;
    }
    int e = blockIdx.x * 256 + threadIdx.x;
    if (e >= N_EDGES) return;
    int s, d;
    if (is64) {
        const long long* p = (const long long*)ei;
        s = (int)p[e]; d = (int)p[N_EDGES + e];
    } else {
        const int* p = (const int*)ei;
        s = p[e]; d = p[N_EDGES + e];
    }
    s = min(max(s, 0), N_NODES - 1);
    d = min(max(d, 0), N_NODES - 1);
    g_edge[e] = (unsigned long long)(unsigned)s |
                ((unsigned long long)(unsigned)d << 32);
    atomicAdd(&g_degi[d], 1);
}

// ---------------- gemm1 (degree-free): h1 = fp16(x@W1); zero agg1 -----------
__global__ __launch_bounds__(256) void gemm1_raw(const float* __restrict__ x,
                                                 const float* __restrict__ W) {
    constexpr int K = 128;
    constexpr int KT = 32;
    constexpr int NPAD = 264;
    __shared__ float Ws[K * 32];
    __shared__ float xs[KT * NPAD];

    int tid = threadIdx.x;
    for (int i = tid; i < K * 8; i += 256)
        ((float4*)Ws)[i] = ((const float4*)W)[i];

    int base = blockIdx.x * 256;
    int tx = tid & 3;
    int ty = tid >> 2;

    unsigned long long acc[4][4];
#pragma unroll
    for (int i = 0; i < 4; i++)
#pragma unroll
        for (int q = 0; q < 4; q++) acc[i][q] = 0ULL;

    int mync = min(base + tid, N_NODES - 1);

#pragma unroll
    for (int kt = 0; kt < K / KT; kt++) {
        const float4* row = (const float4*)(x + (size_t)mync * 128 + kt * KT);
#pragma unroll
        for (int j = 0; j < 8; j++) {
            float4 v = row[j];
            xs[(4 * j + 0) * NPAD + tid] = v.x;
            xs[(4 * j + 1) * NPAD + tid] = v.y;
            xs[(4 * j + 2) * NPAD + tid] = v.z;
            xs[(4 * j + 3) * NPAD + tid] = v.w;
        }
        __syncthreads();
#pragma unroll
        for (int k = 0; k < KT; k++) {
            float4 xv = *(const float4*)&xs[k * NPAD + ty * 4];
            const ulonglong2* wr = (const ulonglong2*)(Ws + (kt * KT + k) * 32 + tx * 8);
            ulonglong2 w0 = wr[0];
            ulonglong2 w1 = wr[1];
            unsigned long long xp0 = pack2(xv.x);
            unsigned long long xp1 = pack2(xv.y);
            unsigned long long xp2 = pack2(xv.z);
            unsigned long long xp3 = pack2(xv.w);
            ffma2(acc[0][0], xp0, w0.x); ffma2(acc[0][1], xp0, w0.y);
            ffma2(acc[0][2], xp0, w1.x); ffma2(acc[0][3], xp0, w1.y);
            ffma2(acc[1][0], xp1, w0.x); ffma2(acc[1][1], xp1, w0.y);
            ffma2(acc[1][2], xp1, w1.x); ffma2(acc[1][3], xp1, w1.y);
            ffma2(acc[2][0], xp2, w0.x); ffma2(acc[2][1], xp2, w0.y);
            ffma2(acc[2][2], xp2, w1.x); ffma2(acc[2][3], xp2, w1.y);
            ffma2(acc[3][0], xp3, w0.x); ffma2(acc[3][1], xp3, w0.y);
            ffma2(acc[3][2], xp3, w1.x); ffma2(acc[3][3], xp3, w1.y);
        }
        __syncthreads();
    }

#pragma unroll
    for (int i = 0; i < 4; i++) {
        int node = base + ty * 4 + i;
        if (node >= N_NODES) break;
        float2 p0 = unpack2(acc[i][0]);
        float2 p1 = unpack2(acc[i][1]);
        float2 p2 = unpack2(acc[i][2]);
        float2 p3 = unpack2(acc[i][3]);
        uint4 t;
        t.x = h2u(__floats2half2_rn(p0.x, p0.y));
        t.y = h2u(__floats2half2_rn(p1.x, p1.y));
        t.z = h2u(__floats2half2_rn(p2.x, p2.y));
        t.w = h2u(__floats2half2_rn(p3.x, p3.y));
        *(uint4*)(g_h1h + (size_t)node * 8 + tx * 2) = t;
        uint4 z; z.x = 0u; z.y = 0u; z.z = 0u; z.w = 0u;
        *(uint4*)(g_agg1h + (size_t)node * 8 + tx * 2) = z;
    }
}

// ---------------- gemm2: in = relu(dis*agg1 + dis^2*h1 + b1); h2'=(in@W2)*dis
__global__ __launch_bounds__(256) void gemm2_tiled(const float* __restrict__ W,
                                                   const float* __restrict__ b1) {
    constexpr int KT = 32;
    constexpr int NPAD = 264;
    __shared__ float Ws[32 * 32];
    __shared__ float xs[KT * NPAD];

    int tid = threadIdx.x;
    for (int i = tid; i < 32 * 8; i += 256)
        ((float4*)Ws)[i] = ((const float4*)W)[i];

    int base = blockIdx.x * 256;
    int tx = tid & 3;
    int ty = tid >> 2;

    unsigned long long acc[4][4];
#pragma unroll
    for (int i = 0; i < 4; i++)
#pragma unroll
        for (int q = 0; q < 4; q++) acc[i][q] = 0ULL;

    int mync = min(base + tid, N_NODES - 1);

    {
        float dis = rsqrtf((float)g_degi[mync] + 1.0f);
        float d2 = dis * dis;
        // uint4 staging loads: 4+4 x 16B instead of 8+8 x 8B
        const uint4* aggp = (const uint4*)(g_agg1h + (size_t)mync * 8);
        const uint4* hp   = (const uint4*)(g_h1h + (size_t)mync * 8);
#pragma unroll
        for (int u = 0; u < 4; u++) {
            uint4 av = aggp[u];
            uint4 hv = hp[u];
            int c0 = u * 8;
            float2 a0 = u2f2(av.x), a1 = u2f2(av.y), a2 = u2f2(av.z), a3 = u2f2(av.w);
            float2 h0 = u2f2(hv.x), h1v = u2f2(hv.y), h2v = u2f2(hv.z), h3 = u2f2(hv.w);
            float4 bA = ((const float4*)b1)[u * 2];
            float4 bB = ((const float4*)b1)[u * 2 + 1];
            xs[(c0 + 0) * NPAD + tid] = fmaxf(fmaf(dis, a0.x, fmaf(d2, h0.x,  bA.x)), 0.f);
            xs[(c0 + 1) * NPAD + tid] = fmaxf(fmaf(dis, a0.y, fmaf(d2, h0.y,  bA.y)), 0.f);
            xs[(c0 + 2) * NPAD + tid] = fmaxf(fmaf(dis, a1.x, fmaf(d2, h1v.x, bA.z)), 0.f);
            xs[(c0 + 3) * NPAD + tid] = fmaxf(fmaf(dis, a1.y, fmaf(d2, h1v.y, bA.w)), 0.f);
            xs[(c0 + 4) * NPAD + tid] = fmaxf(fmaf(dis, a2.x, fmaf(d2, h2v.x, bB.x)), 0.f);
            xs[(c0 + 5) * NPAD + tid] = fmaxf(fmaf(dis, a2.y, fmaf(d2, h2v.y, bB.y)), 0.f);
            xs[(c0 + 6) * NPAD + tid] = fmaxf(fmaf(dis, a3.x, fmaf(d2, h3.x,  bB.z)), 0.f);
            xs[(c0 + 7) * NPAD + tid] = fmaxf(fmaf(dis, a3.y, fmaf(d2, h3.y,  bB.w)), 0.f);
        }
    }
    __syncthreads();

#pragma unroll
    for (int k = 0; k < KT; k++) {
        float4 xv = *(const float4*)&xs[k * NPAD + ty * 4];
        const ulonglong2* wr = (const ulonglong2*)(Ws + k * 32 + tx * 8);
        ulonglong2 w0 = wr[0];
        ulonglong2 w1 = wr[1];
        unsigned long long xp0 = pack2(xv.x);
        unsigned long long xp1 = pack2(xv.y);
        unsigned long long xp2 = pack2(xv.z);
        unsigned long long xp3 = pack2(xv.w);
        ffma2(acc[0][0], xp0, w0.x); ffma2(acc[0][1], xp0, w0.y);
        ffma2(acc[0][2], xp0, w1.x); ffma2(acc[0][3], xp0, w1.y);
        ffma2(acc[1][0], xp1, w0.x); ffma2(acc[1][1], xp1, w0.y);
        ffma2(acc[1][2], xp1, w1.x); ffma2(acc[1][3], xp1, w1.y);
        ffma2(acc[2][0], xp2, w0.x); ffma2(acc[2][1], xp2, w0.y);
        ffma2(acc[2][2], xp2, w1.x); ffma2(acc[2][3], xp2, w1.y);
        ffma2(acc[3][0], xp3, w0.x); ffma2(acc[3][1], xp3, w0.y);
        ffma2(acc[3][2], xp3, w1.x); ffma2(acc[3][3], xp3, w1.y);
    }

#pragma unroll
    for (int i = 0; i < 4; i++) {
        int node = base + ty * 4 + i;
        if (node >= N_NODES) break;
        float dis = rsqrtf((float)g_degi[node] + 1.0f);
        float2 p0 = unpack2(acc[i][0]);
        float2 p1 = unpack2(acc[i][1]);
        float2 p2 = unpack2(acc[i][2]);
        float2 p3 = unpack2(acc[i][3]);
        uint4 t;
        t.x = h2u(__floats2half2_rn(p0.x * dis, p0.y * dis));
        t.y = h2u(__floats2half2_rn(p1.x * dis, p1.y * dis));
        t.z = h2u(__floats2half2_rn(p2.x * dis, p2.y * dis));
        t.w = h2u(__floats2half2_rn(p3.x * dis, p3.y * dis));
        *(uint4*)(g_h2h + (size_t)node * 8 + tx * 2) = t;
        uint4 z; z.x = 0u; z.y = 0u; z.z = 0u; z.w = 0u;
        *(uint4*)(g_agg2h + (size_t)node * 8 + tx * 2) = z;
    }
}

// ---------------- edge scatter: agg[dst] += h[src] (*dis[src] on layer 1) ----
// 4 lanes per edge (16B v4.f16x2 red); 8 independent edges/thread (MLP=8)
// LAYER 1 computes dis[src] inline from g_degi (no dis table / kernel).
template <int LAYER>
__global__ __launch_bounds__(256) void scatter_kernel() {
    const uint4* h = (LAYER == 1) ? (const uint4*)g_h1h : (const uint4*)g_h2h;
    uint4* agg = (LAYER == 1) ? (uint4*)g_agg1h : (uint4*)g_agg2h;
    const int Q = N_EDGES / 8;

    int idx = blockIdx.x * 256 + threadIdx.x;
    int e0 = idx >> 2;
    if (e0 >= Q) return;
    int c = idx & 3;   // quarter-row: 16B = 1 uint4

    unsigned long long ed[8];
#pragma unroll
    for (int j = 0; j < 8; j++) ed[j] = g_edge[e0 + j * Q];

    uint4 v[8];
#pragma unroll
    for (int j = 0; j < 8; j++)
        v[j] = h[(size_t)(unsigned)(ed[j] & 0xffffffffu) * 4 + c];

    if (LAYER == 1) {
        __half2 dd[8];
#pragma unroll
        for (int j = 0; j < 8; j++) {
            float dg = (float)g_degi[(unsigned)(ed[j] & 0xffffffffu)];
            dd[j] = __half2half2(__float2half(rsqrtf(dg + 1.0f)));
        }
#pragma unroll
        for (int j = 0; j < 8; j++) {
            v[j].x = h2u(__hmul2(u2h2(v[j].x), dd[j]));
            v[j].y = h2u(__hmul2(u2h2(v[j].y), dd[j]));
            v[j].z = h2u(__hmul2(u2h2(v[j].z), dd[j]));
            v[j].w = h2u(__hmul2(u2h2(v[j].w), dd[j]));
        }
    }

#pragma unroll
    for (int j = 0; j < 8; j++) {
        uint4* p = agg + (size_t)(unsigned)(ed[j] >> 32) * 4 + c;
        asm volatile("red.global.add.noftz.v4.f16x2 [%0], {%1,%2,%3,%4};"
                     :: "l"(p), "r"(v[j].x), "r"(v[j].y), "r"(v[j].z), "r"(v[j].w)
                     : "memory");
    }
}

// ---------------- pool: 4 threads/node, shfl reduce, fused final ------------
// Also re-zeroes g_degi for the next graph replay (lane 3, after all reads).
__global__ void pool_kernel(const void* ei, const void* batch,
                            const float* __restrict__ b2,
                            const float* __restrict__ Wo,
                            const float* __restrict__ bo,
                            float* __restrict__ out) {
    int is64 = detect_is64(ei);
    int idx = blockIdx.x * 256 + threadIdx.x;
    int n = idx >> 2;
    int q = idx & 3;
    if (n < N_NODES) {
        float dis = rsqrtf((float)g_degi[n] + 1.0f);   // all 4 lanes load (same warp)
        if (q == 3) g_degi[n] = 0;                      // program-order after loads
        uint4 av = ((const uint4*)(g_agg2h + (size_t)n * 8))[q];
        uint4 hv = ((const uint4*)(g_h2h + (size_t)n * 8))[q];
        float4 bA = ((const float4*)b2)[q * 2];
        float4 bB = ((const float4*)b2)[q * 2 + 1];
        float4 wA = ((const float4*)Wo)[q * 2];
        float4 wB = ((const float4*)Wo)[q * 2 + 1];
        float2 a0 = u2f2(av.x), a1 = u2f2(av.y), a2 = u2f2(av.z), a3 = u2f2(av.w);
        float2 h0 = u2f2(hv.x), h1v = u2f2(hv.y), h2v = u2f2(hv.z), h3 = u2f2(hv.w);
        float s = 0.f;
        s += fmaxf(fmaf(dis, a0.x + h0.x,  bA.x), 0.f) * wA.x;
        s += fmaxf(fmaf(dis, a0.y + h0.y,  bA.y), 0.f) * wA.y;
        s += fmaxf(fmaf(dis, a1.x + h1v.x, bA.z), 0.f) * wA.z;
        s += fmaxf(fmaf(dis, a1.y + h1v.y, bA.w), 0.f) * wA.w;
        s += fmaxf(fmaf(dis, a2.x + h2v.x, bB.x), 0.f) * wB.x;
        s += fmaxf(fmaf(dis, a2.y + h2v.y, bB.y), 0.f) * wB.y;
        s += fmaxf(fmaf(dis, a3.x + h3.x,  bB.z), 0.f) * wB.z;
        s += fmaxf(fmaf(dis, a3.y + h3.y,  bB.w), 0.f) * wB.w;
        // reduce across the 4 lanes of this node
        s += __shfl_xor_sync(0xffffffffu, s, 1);
        s += __shfl_xor_sync(0xffffffffu, s, 2);
        if (q == 0) {
            int g;
            if (is64) g = (int)((const long long*)batch)[n];
            else      g = ((const int*)batch)[n];
            g = min(max(g, 0), N_GRAPHS - 1);
            atomicAdd(&g_gsum[g], s);
            atomicAdd(&g_gcnt[g], 1.0f);
        }
    }

    // last-block finalize
    __threadfence();
    __syncthreads();
    __shared__ int s_last;
    if (threadIdx.x == 0) {
        int t = atomicAdd(&g_done, 1);
        s_last = (t == (int)gridDim.x - 1) ? 1 : 0;
    }
    __syncthreads();
    if (s_last) {
        float bias = bo[0];
        for (int i = threadIdx.x; i < N_GRAPHS; i += 256) {
            float sv = atomicAdd(&g_gsum[i], 0.0f);   // coherent read
            float cv = atomicAdd(&g_gcnt[i], 0.0f);
            out[i] = sv / fmaxf(cv, 1.0f) + bias;
        }
        __syncthreads();
        if (threadIdx.x == 0) g_done = 0;   // self-reset for graph replay
    }
}

// ---------------- launch ----------------------------------------------------
extern "C" void kernel_launch(void* const* d_in, const int* in_sizes, int n_in,
                              void* d_out, int out_size) {
    const float* x   = (const float*)d_in[0];
    const void*  ei  = d_in[1];
    const void*  bat = d_in[2];
    const float* W1  = (const float*)d_in[3];
    const float* b1  = (const float*)d_in[4];
    const float* W2  = (const float*)d_in[5];
    const float* b2  = (const float*)d_in[6];
    const float* Wo  = (const float*)d_in[7];
    const float* bo  = (const float*)d_in[8];
    float* out = (float*)d_out;

    // one-time resources (created on the eager correctness call, before capture)
    static cudaStream_t sB = nullptr;
    static cudaEvent_t evF = nullptr, evJ = nullptr;
    if (!sB) {
        cudaStreamCreateWithFlags(&sB, cudaStreamNonBlocking);
        cudaEventCreateWithFlags(&evF, cudaEventDisableTiming);
        cudaEventCreateWithFlags(&evJ, cudaEventDisableTiming);
    }

    const int GB = (N_NODES + 255) / 256;   // 391

    // fork: gemm1 (degree-free) runs concurrently with prep
    cudaEventRecord(evF, 0);
    cudaStreamWaitEvent(sB, evF, 0);
    gemm1_raw<<<GB, 256, 0, sB>>>(x, W1);

    prep_kernel<<<(N_EDGES + 255) / 256, 256>>>(ei);

    // join
    cudaEventRecord(evJ, sB);
    cudaStreamWaitEvent(0, evJ, 0);

    // layer 1 scatter (dis[src] computed inline from degrees, MLP=8)
    scatter_kernel<1><<<(N_EDGES / 8 * 4 + 255) / 256, 256>>>();

    // layer 2
    gemm2_tiled<<<GB, 256>>>(W2, b1);
    scatter_kernel<2><<<(N_EDGES / 8 * 4 + 255) / 256, 256>>>();

    // pooling + head (final fold via last-block; re-zeroes g_degi for replay)
    pool_kernel<<<(N_NODES * 4 + 255) / 256, 256>>>(ei, bat, b2, Wo, bo, out);
}

// round 16
// speedup vs baseline: 1.0021x; 1.0021x over previous
#include <cuda_runtime.h>
#include <cuda_fp16.h>
#include <cstdint>

#define N_NODES 100000
#define N_EDGES 1600000
#define N_GRAPHS 512

// ---------------- scratch (device globals; no allocation allowed) ----------
// g_degi is zero on first run (static init) and re-zeroed by pool_kernel at
// the end of every replay -> deterministic across graph replays.
__device__ int                g_degi[N_NODES];
__device__ unsigned long long g_edge[N_EDGES];     // packed src | dst<<32
__device__ uint2              g_h1h[N_NODES * 8];  // h1 = x@W1 (UNSCALED), fp16
__device__ uint2              g_agg1h[N_NODES * 8];// fp16 accumulators
__device__ uint2              g_h2h[N_NODES * 8];  // h2' = (in@W2)*dis, fp16
__device__ uint2              g_agg2h[N_NODES * 8];
__device__ float              g_gsum[N_GRAPHS];
__device__ float              g_gcnt[N_GRAPHS];
__device__ int                g_done;

// ---------------- f32x2 helpers (Blackwell packed FFMA) ---------------------
__device__ __forceinline__ unsigned long long pack2(float x) {
    unsigned long long r;
    asm("mov.b64 %0, {%1, %1};" : "=l"(r) : "r"(__float_as_uint(x)));
    return r;
}
__device__ __forceinline__ void ffma2(unsigned long long& d,
                                      unsigned long long a,
                                      unsigned long long b) {
    asm("fma.rn.f32x2 %0, %1, %2, %0;" : "+l"(d) : "l"(a), "l"(b));
}
__device__ __forceinline__ float2 unpack2(unsigned long long v) {
    float2 f;
    asm("mov.b64 {%0, %1}, %2;" : "=f"(f.x), "=f"(f.y) : "l"(v));
    return f;
}
__device__ __forceinline__ unsigned h2u(__half2 h) { return *(unsigned*)&h; }
__device__ __forceinline__ __half2 u2h2(unsigned u) { return *(__half2*)&u; }
__device__ __forceinline__ float2 u2f2(unsigned u) {
    return __half22float2(*(__half2*)&u);
}

// per-block dtype detection: warp ballot over first 64 u64 words of edge_index
__device__ __forceinline__ int detect_is64(const void* ei) {
    __shared__ int s_is64;
    if (threadIdx.x < 32) {
        const unsigned long long* p = (const unsigned long long*)ei;
        unsigned long long v0 = p[threadIdx.x];
        unsigned long long v1 = p[32 + threadIdx.x];
        unsigned m = __ballot_sync(0xffffffffu,
            (v0 >= (unsigned long long)N_NODES) || (v1 >= (unsigned long long)N_NODES));
        if (threadIdx.x == 0) s_is64 = m ? 0 : 1;
    }
    __syncthreads();
    return s_is64;
}

// ---------------- prep: detect + pack edges + degree hist + zero smalls -----
__global__ void prep_kernel(const void* ei) {
    int is64 = detect_is64(ei);
    if (blockIdx.x == 0) {
        for (int i = threadIdx.x; i < N_GRAPHS; i += 256) {
            g_gsum[i] = 0.f; g_gcnt[i] = 0.f;
        }
        if (threadIdx.x == 0) g_done = 0;
    }
    int e = blockIdx.x * 256 + threadIdx.x;
    if (e >= N_EDGES) return;
    int s, d;
    if (is64) {
        const long long* p = (const long long*)ei;
        s = (int)p[e]; d = (int)p[N_EDGES + e];
    } else {
        const int* p = (const int*)ei;
        s = p[e]; d = p[N_EDGES + e];
    }
    s = min(max(s, 0), N_NODES - 1);
    d = min(max(d, 0), N_NODES - 1);
    g_edge[e] = (unsigned long long)(unsigned)s |
                ((unsigned long long)(unsigned)d << 32);
    atomicAdd(&g_degi[d], 1);
}

// ---------------- gemm1 (degree-free): h1 = fp16(x@W1); zero agg1 -----------
__global__ __launch_bounds__(256) void gemm1_raw(const float* __restrict__ x,
                                                 const float* __restrict__ W) {
    constexpr int K = 128;
    constexpr int KT = 32;
    constexpr int NPAD = 264;
    __shared__ float Ws[K * 32];
    __shared__ float xs[KT * NPAD];

    int tid = threadIdx.x;
    for (int i = tid; i < K * 8; i += 256)
        ((float4*)Ws)[i] = ((const float4*)W)[i];

    int base = blockIdx.x * 256;
    int tx = tid & 3;
    int ty = tid >> 2;

    unsigned long long acc[4][4];
#pragma unroll
    for (int i = 0; i < 4; i++)
#pragma unroll
        for (int q = 0; q < 4; q++) acc[i][q] = 0ULL;

    int mync = min(base + tid, N_NODES - 1);

#pragma unroll
    for (int kt = 0; kt < K / KT; kt++) {
        const float4* row = (const float4*)(x + (size_t)mync * 128 + kt * KT);
#pragma unroll
        for (int j = 0; j < 8; j++) {
            float4 v = row[j];
            xs[(4 * j + 0) * NPAD + tid] = v.x;
            xs[(4 * j + 1) * NPAD + tid] = v.y;
            xs[(4 * j + 2) * NPAD + tid] = v.z;
            xs[(4 * j + 3) * NPAD + tid] = v.w;
        }
        __syncthreads();
#pragma unroll
        for (int k = 0; k < KT; k++) {
            float4 xv = *(const float4*)&xs[k * NPAD + ty * 4];
            const ulonglong2* wr = (const ulonglong2*)(Ws + (kt * KT + k) * 32 + tx * 8);
            ulonglong2 w0 = wr[0];
            ulonglong2 w1 = wr[1];
            unsigned long long xp0 = pack2(xv.x);
            unsigned long long xp1 = pack2(xv.y);
            unsigned long long xp2 = pack2(xv.z);
            unsigned long long xp3 = pack2(xv.w);
            ffma2(acc[0][0], xp0, w0.x); ffma2(acc[0][1], xp0, w0.y);
            ffma2(acc[0][2], xp0, w1.x); ffma2(acc[0][3], xp0, w1.y);
            ffma2(acc[1][0], xp1, w0.x); ffma2(acc[1][1], xp1, w0.y);
            ffma2(acc[1][2], xp1, w1.x); ffma2(acc[1][3], xp1, w1.y);
            ffma2(acc[2][0], xp2, w0.x); ffma2(acc[2][1], xp2, w0.y);
            ffma2(acc[2][2], xp2, w1.x); ffma2(acc[2][3], xp2, w1.y);
            ffma2(acc[3][0], xp3, w0.x); ffma2(acc[3][1], xp3, w0.y);
            ffma2(acc[3][2], xp3, w1.x); ffma2(acc[3][3], xp3, w1.y);
        }
        __syncthreads();
    }

#pragma unroll
    for (int i = 0; i < 4; i++) {
        int node = base + ty * 4 + i;
        if (node >= N_NODES) break;
        float2 p0 = unpack2(acc[i][0]);
        float2 p1 = unpack2(acc[i][1]);
        float2 p2 = unpack2(acc[i][2]);
        float2 p3 = unpack2(acc[i][3]);
        uint4 t;
        t.x = h2u(__floats2half2_rn(p0.x, p0.y));
        t.y = h2u(__floats2half2_rn(p1.x, p1.y));
        t.z = h2u(__floats2half2_rn(p2.x, p2.y));
        t.w = h2u(__floats2half2_rn(p3.x, p3.y));
        *(uint4*)(g_h1h + (size_t)node * 8 + tx * 2) = t;
        uint4 z; z.x = 0u; z.y = 0u; z.z = 0u; z.w = 0u;
        *(uint4*)(g_agg1h + (size_t)node * 8 + tx * 2) = z;
    }
}

// ---------------- gemm2: in = relu(dis*agg1 + dis^2*h1 + b1); h2'=(in@W2)*dis
__global__ __launch_bounds__(256) void gemm2_tiled(const float* __restrict__ W,
                                                   const float* __restrict__ b1) {
    constexpr int KT = 32;
    constexpr int NPAD = 264;
    __shared__ float Ws[32 * 32];
    __shared__ float xs[KT * NPAD];

    int tid = threadIdx.x;
    for (int i = tid; i < 32 * 8; i += 256)
        ((float4*)Ws)[i] = ((const float4*)W)[i];

    int base = blockIdx.x * 256;
    int tx = tid & 3;
    int ty = tid >> 2;

    unsigned long long acc[4][4];
#pragma unroll
    for (int i = 0; i < 4; i++)
#pragma unroll
        for (int q = 0; q < 4; q++) acc[i][q] = 0ULL;

    int mync = min(base + tid, N_NODES - 1);

    {
        float dis = rsqrtf((float)g_degi[mync] + 1.0f);
        float d2 = dis * dis;
        // uint4 staging loads: 4+4 x 16B (measured win in R15)
        const uint4* aggp = (const uint4*)(g_agg1h + (size_t)mync * 8);
        const uint4* hp   = (const uint4*)(g_h1h + (size_t)mync * 8);
#pragma unroll
        for (int u = 0; u < 4; u++) {
            uint4 av = aggp[u];
            uint4 hv = hp[u];
            int c0 = u * 8;
            float2 a0 = u2f2(av.x), a1 = u2f2(av.y), a2 = u2f2(av.z), a3 = u2f2(av.w);
            float2 h0 = u2f2(hv.x), h1v = u2f2(hv.y), h2v = u2f2(hv.z), h3 = u2f2(hv.w);
            float4 bA = ((const float4*)b1)[u * 2];
            float4 bB = ((const float4*)b1)[u * 2 + 1];
            xs[(c0 + 0) * NPAD + tid] = fmaxf(fmaf(dis, a0.x, fmaf(d2, h0.x,  bA.x)), 0.f);
            xs[(c0 + 1) * NPAD + tid] = fmaxf(fmaf(dis, a0.y, fmaf(d2, h0.y,  bA.y)), 0.f);
            xs[(c0 + 2) * NPAD + tid] = fmaxf(fmaf(dis, a1.x, fmaf(d2, h1v.x, bA.z)), 0.f);
            xs[(c0 + 3) * NPAD + tid] = fmaxf(fmaf(dis, a1.y, fmaf(d2, h1v.y, bA.w)), 0.f);
            xs[(c0 + 4) * NPAD + tid] = fmaxf(fmaf(dis, a2.x, fmaf(d2, h2v.x, bB.x)), 0.f);
            xs[(c0 + 5) * NPAD + tid] = fmaxf(fmaf(dis, a2.y, fmaf(d2, h2v.y, bB.y)), 0.f);
            xs[(c0 + 6) * NPAD + tid] = fmaxf(fmaf(dis, a3.x, fmaf(d2, h3.x,  bB.z)), 0.f);
            xs[(c0 + 7) * NPAD + tid] = fmaxf(fmaf(dis, a3.y, fmaf(d2, h3.y,  bB.w)), 0.f);
        }
    }
    __syncthreads();

#pragma unroll
    for (int k = 0; k < KT; k++) {
        float4 xv = *(const float4*)&xs[k * NPAD + ty * 4];
        const ulonglong2* wr = (const ulonglong2*)(Ws + k * 32 + tx * 8);
        ulonglong2 w0 = wr[0];
        ulonglong2 w1 = wr[1];
        unsigned long long xp0 = pack2(xv.x);
        unsigned long long xp1 = pack2(xv.y);
        unsigned long long xp2 = pack2(xv.z);
        unsigned long long xp3 = pack2(xv.w);
        ffma2(acc[0][0], xp0, w0.x); ffma2(acc[0][1], xp0, w0.y);
        ffma2(acc[0][2], xp0, w1.x); ffma2(acc[0][3], xp0, w1.y);
        ffma2(acc[1][0], xp1, w0.x); ffma2(acc[1][1], xp1, w0.y);
        ffma2(acc[1][2], xp1, w1.x); ffma2(acc[1][3], xp1, w1.y);
        ffma2(acc[2][0], xp2, w0.x); ffma2(acc[2][1], xp2, w0.y);
        ffma2(acc[2][2], xp2, w1.x); ffma2(acc[2][3], xp2, w1.y);
        ffma2(acc[3][0], xp3, w0.x); ffma2(acc[3][1], xp3, w0.y);
        ffma2(acc[3][2], xp3, w1.x); ffma2(acc[3][3], xp3, w1.y);
    }

#pragma unroll
    for (int i = 0; i < 4; i++) {
        int node = base + ty * 4 + i;
        if (node >= N_NODES) break;
        float dis = rsqrtf((float)g_degi[node] + 1.0f);
        float2 p0 = unpack2(acc[i][0]);
        float2 p1 = unpack2(acc[i][1]);
        float2 p2 = unpack2(acc[i][2]);
        float2 p3 = unpack2(acc[i][3]);
        uint4 t;
        t.x = h2u(__floats2half2_rn(p0.x * dis, p0.y * dis));
        t.y = h2u(__floats2half2_rn(p1.x * dis, p1.y * dis));
        t.z = h2u(__floats2half2_rn(p2.x * dis, p2.y * dis));
        t.w = h2u(__floats2half2_rn(p3.x * dis, p3.y * dis));
        *(uint4*)(g_h2h + (size_t)node * 8 + tx * 2) = t;
        uint4 z; z.x = 0u; z.y = 0u; z.z = 0u; z.w = 0u;
        *(uint4*)(g_agg2h + (size_t)node * 8 + tx * 2) = z;
    }
}

// ---------------- edge scatter: agg[dst] += h[src] (*dis[src] on layer 1) ----
// 4 lanes per edge (16B v4.f16x2 red); 4 independent edges/thread (MLP=4;
// measured best in R13/14 — MLP=8 regressed slightly in R15)
template <int LAYER>
__global__ __launch_bounds__(256) void scatter_kernel() {
    const uint4* h = (LAYER == 1) ? (const uint4*)g_h1h : (const uint4*)g_h2h;
    uint4* agg = (LAYER == 1) ? (uint4*)g_agg1h : (uint4*)g_agg2h;
    const int Q = N_EDGES / 4;

    int idx = blockIdx.x * 256 + threadIdx.x;
    int e0 = idx >> 2;
    if (e0 >= Q) return;
    int c = idx & 3;   // quarter-row: 16B = 1 uint4

    unsigned long long ed[4];
#pragma unroll
    for (int j = 0; j < 4; j++) ed[j] = g_edge[e0 + j * Q];

    uint4 v[4];
    __half2 dd[4];
#pragma unroll
    for (int j = 0; j < 4; j++) {
        unsigned s = (unsigned)(ed[j] & 0xffffffffu);
        v[j] = h[(size_t)s * 4 + c];
        if (LAYER == 1) {
            float dg = (float)g_degi[s];
            dd[j] = __half2half2(__float2half(rsqrtf(dg + 1.0f)));
        }
    }

    if (LAYER == 1) {
#pragma unroll
        for (int j = 0; j < 4; j++) {
            v[j].x = h2u(__hmul2(u2h2(v[j].x), dd[j]));
            v[j].y = h2u(__hmul2(u2h2(v[j].y), dd[j]));
            v[j].z = h2u(__hmul2(u2h2(v[j].z), dd[j]));
            v[j].w = h2u(__hmul2(u2h2(v[j].w), dd[j]));
        }
    }

#pragma unroll
    for (int j = 0; j < 4; j++) {
        uint4* p = agg + (size_t)(unsigned)(ed[j] >> 32) * 4 + c;
        asm volatile("red.global.add.noftz.v4.f16x2 [%0], {%1,%2,%3,%4};"
                     :: "l"(p), "r"(v[j].x), "r"(v[j].y), "r"(v[j].z), "r"(v[j].w)
                     : "memory");
    }
}

// ---------------- pool: 4 threads/node, shfl reduce, fused final ------------
// Also re-zeroes g_degi for the next graph replay (lane 3, after all reads).
__global__ void pool_kernel(const void* ei, const void* batch,
                            const float* __restrict__ b2,
                            const float* __restrict__ Wo,
                            const float* __restrict__ bo,
                            float* __restrict__ out) {
    int is64 = detect_is64(ei);
    int idx = blockIdx.x * 256 + threadIdx.x;
    int n = idx >> 2;
    int q = idx & 3;
    if (n < N_NODES) {
        float dis = rsqrtf((float)g_degi[n] + 1.0f);   // all 4 lanes load (same warp)
        if (q == 3) g_degi[n] = 0;                      // program-order after loads
        uint4 av = ((const uint4*)(g_agg2h + (size_t)n * 8))[q];
        uint4 hv = ((const uint4*)(g_h2h + (size_t)n * 8))[q];
        float4 bA = ((const float4*)b2)[q * 2];
        float4 bB = ((const float4*)b2)[q * 2 + 1];
        float4 wA = ((const float4*)Wo)[q * 2];
        float4 wB = ((const float4*)Wo)[q * 2 + 1];
        float2 a0 = u2f2(av.x), a1 = u2f2(av.y), a2 = u2f2(av.z), a3 = u2f2(av.w);
        float2 h0 = u2f2(hv.x), h1v = u2f2(hv.y), h2v = u2f2(hv.z), h3 = u2f2(hv.w);
        float s = 0.f;
        s += fmaxf(fmaf(dis, a0.x + h0.x,  bA.x), 0.f) * wA.x;
        s += fmaxf(fmaf(dis, a0.y + h0.y,  bA.y), 0.f) * wA.y;
        s += fmaxf(fmaf(dis, a1.x + h1v.x, bA.z), 0.f) * wA.z;
        s += fmaxf(fmaf(dis, a1.y + h1v.y, bA.w), 0.f) * wA.w;
        s += fmaxf(fmaf(dis, a2.x + h2v.x, bB.x), 0.f) * wB.x;
        s += fmaxf(fmaf(dis, a2.y + h2v.y, bB.y), 0.f) * wB.y;
        s += fmaxf(fmaf(dis, a3.x + h3.x,  bB.z), 0.f) * wB.z;
        s += fmaxf(fmaf(dis, a3.y + h3.y,  bB.w), 0.f) * wB.w;
        // reduce across the 4 lanes of this node
        s += __shfl_xor_sync(0xffffffffu, s, 1);
        s += __shfl_xor_sync(0xffffffffu, s, 2);
        if (q == 0) {
            int g;
            if (is64) g = (int)((const long long*)batch)[n];
            else      g = ((const int*)batch)[n];
            g = min(max(g, 0), N_GRAPHS - 1);
            atomicAdd(&g_gsum[g], s);
            atomicAdd(&g_gcnt[g], 1.0f);
        }
    }

    // last-block finalize
    __threadfence();
    __syncthreads();
    __shared__ int s_last;
    if (threadIdx.x == 0) {
        int t = atomicAdd(&g_done, 1);
        s_last = (t == (int)gridDim.x - 1) ? 1 : 0;
    }
    __syncthreads();
    if (s_last) {
        float bias = bo[0];
        for (int i = threadIdx.x; i < N_GRAPHS; i += 256) {
            float sv = atomicAdd(&g_gsum[i], 0.0f);   // coherent read
            float cv = atomicAdd(&g_gcnt[i], 0.0f);
            out[i] = sv / fmaxf(cv, 1.0f) + bias;
        }
        __syncthreads();
        if (threadIdx.x == 0) g_done = 0;   // self-reset for graph replay
    }
}

// ---------------- launch ----------------------------------------------------
extern "C" void kernel_launch(void* const* d_in, const int* in_sizes, int n_in,
                              void* d_out, int out_size) {
    const float* x   = (const float*)d_in[0];
    const void*  ei  = d_in[1];
    const void*  bat = d_in[2];
    const float* W1  = (const float*)d_in[3];
    const float* b1  = (const float*)d_in[4];
    const float* W2  = (const float*)d_in[5];
    const float* b2  = (const float*)d_in[6];
    const float* Wo  = (const float*)d_in[7];
    const float* bo  = (const float*)d_in[8];
    float* out = (float*)d_out;

    // one-time resources (created on the eager correctness call, before capture)
    static cudaStream_t sB = nullptr;
    static cudaEvent_t evF = nullptr, evJ = nullptr;
    if (!sB) {
        cudaStreamCreateWithFlags(&sB, cudaStreamNonBlocking);
        cudaEventCreateWithFlags(&evF, cudaEventDisableTiming);
        cudaEventCreateWithFlags(&evJ, cudaEventDisableTiming);
    }

    const int GB = (N_NODES + 255) / 256;   // 391

    // fork: gemm1 (degree-free) runs concurrently with prep
    cudaEventRecord(evF, 0);
    cudaStreamWaitEvent(sB, evF, 0);
    gemm1_raw<<<GB, 256, 0, sB>>>(x, W1);

    prep_kernel<<<(N_EDGES + 255) / 256, 256>>>(ei);

    // join
    cudaEventRecord(evJ, sB);
    cudaStreamWaitEvent(0, evJ, 0);

    // layer 1 scatter (dis[src] computed inline from degrees, MLP=4)
    scatter_kernel<1><<<(N_EDGES + 255) / 256, 256>>>();

    // layer 2
    gemm2_tiled<<<GB, 256>>>(W2, b1);
    scatter_kernel<2><<<(N_EDGES + 255) / 256, 256>>>();

    // pooling + head (final fold via last-block; re-zeroes g_degi for replay)
    pool_kernel<<<(N_NODES * 4 + 255) / 256, 256>>>(ei, bat, b2, Wo, bo, out);
}